// round 11
// baseline (speedup 1.0000x reference)
#include <cuda_runtime.h>
#include <cstdint>

#define FULL 0xffffffffu
typedef unsigned long long ull;
typedef ulonglong2 ull2;

// Problem dims
constexpr int Bb = 512;
constexpr int Vv = 64;
constexpr int Aa = 8;
constexpr int Ee = Vv * (Vv - 1);   // 4032

// Output layout: [tanh_mu B*V*A][logp B*V][aug B*V*96]
constexpr size_t OUT_TANH = 0;
constexpr size_t OUT_LOGP = (size_t)Bb * Vv * Aa;          // 262144
constexpr size_t OUT_AUG  = OUT_LOGP + (size_t)Bb * Vv;    // 294912

__device__ __forceinline__ float relu(float x) { return fmaxf(x, 0.0f); }

constexpr float HALF_LOG_2PI_F = 0.91893853320467274f;
constexpr float LOG2_F         = 0.69314718055994531f;

// ---- packed fp32x2 helpers ----
__device__ __forceinline__ ull fma2(ull a, ull b, ull c) {
    ull d;
    asm("fma.rn.f32x2 %0, %1, %2, %3;" : "=l"(d) : "l"(a), "l"(b), "l"(c));
    return d;
}
__device__ __forceinline__ ull packdup(float x) {
    ull d;
    asm("mov.b64 %0, {%1, %1};" : "=l"(d) : "f"(x));
    return d;
}
__device__ __forceinline__ ull pack2(float lo, float hi) {
    ull d;
    asm("mov.b64 %0, {%1, %2};" : "=l"(d) : "f"(lo), "f"(hi));
    return d;
}
// pack two fp32 into half2: lo -> bits[15:0], hi -> bits[31:16]
__device__ __forceinline__ uint32_t packh2(float lo, float hi) {
    uint32_t d;
    asm("cvt.rn.f16x2.f32 %0, %1, %2;" : "=r"(d) : "f"(hi), "f"(lo));
    return d;
}

// m16n8k16 f16 mma, f32 accumulate (sm_80+ path, legal on plain sm_103)
__device__ __forceinline__ void mma_f16(float c[4], const uint32_t a[4],
                                        uint32_t b0, uint32_t b1) {
    asm volatile(
        "mma.sync.aligned.m16n8k16.row.col.f32.f16.f16.f32 "
        "{%0,%1,%2,%3}, {%4,%5,%6,%7}, {%8,%9}, {%0,%1,%2,%3};"
        : "+f"(c[0]), "+f"(c[1]), "+f"(c[2]), "+f"(c[3])
        : "r"(a[0]), "r"(a[1]), "r"(a[2]), "r"(a[3]), "r"(b0), "r"(b1));
}

// ============================================================================
// Kernel 1: FUSED mlp1 + edge MLP2 (fp16 mma) + fp32 aggregation.
// Block = one batch. Prologue computes hb/hs per warp (8 nodes each) with the
// exact mlp1 shfl+fma2 sequence and writes aug[:,0:32]; main loop unchanged.
// ============================================================================
constexpr int SHS   = 0;                  // hs [64][68] padded (floats)
constexpr int SHB   = SHS + 64 * 68;      // hb [64][64]
constexpr int SBF   = SHB + 64 * 64;      // B frags: 32 frags x 64 lanes x ull
constexpr int SEW   = SBF + 32 * 64 * 2;  // ew [64][64]
constexpr int SBIAS = SEW + 64 * 64;      // [64]
constexpr int SW1R  = SBIAS + 64;         // m1w recv-half packed: 1024 ull
constexpr int SW1S  = SW1R + 1024 * 2;    // m1w send-half packed: 1024 ull
constexpr int SB1   = SW1S + 1024 * 2;    // m1b packed: 32 ull
constexpr int EDGE_SMEM_F = SB1 + 64;
constexpr int EDGE_SMEM_B = EDGE_SMEM_F * 4;   // ~83.5 KB

__global__ __launch_bounds__(256, 2) void edge_kernel(
    const float* __restrict__ inputs,   // [B,V,32]
    const float* __restrict__ edges,    // [B,E,2]
    const float* __restrict__ m1w,      // [64,64]
    const float* __restrict__ m1b,      // [64]
    const float* __restrict__ m2w,      // [64,64]
    const float* __restrict__ m2b,      // [64]
    float* __restrict__ out)
{
    extern __shared__ float sf[];
    ull* sfu  = reinterpret_cast<ull*>(&sf[SBF]);
    ull* w1r  = reinterpret_cast<ull*>(&sf[SW1R]);
    ull* w1s  = reinterpret_cast<ull*>(&sf[SW1S]);
    ull* sb1p = reinterpret_cast<ull*>(&sf[SB1]);

    const int b    = blockIdx.x;
    const int tid  = threadIdx.x;
    const int lane = tid & 31;
    const int w    = tid >> 5;
    const int g    = lane >> 2;   // group id (rows / n-cols)
    const int tig  = lane & 3;    // thread in group

    // ---- prologue A: stage weights, B frags, edge weights, biases ----
    {
        for (int i = tid; i < 1024; i += 256) {
            int k = i >> 5, c = i & 31;
            w1r[i] = pack2(m1w[k * 64 + c],        m1w[k * 64 + c + 32]);
            w1s[i] = pack2(m1w[(32 + k) * 64 + c], m1w[(32 + k) * 64 + c + 32]);
        }
        if (tid < 32) sb1p[tid] = pack2(m1b[tid], m1b[tid + 32]);

        // B fragments (fragment-major, fp16)
        for (int i = tid; i < 2048; i += 256) {
            int frag = i >> 6, li = i & 63;
            int nt = frag >> 2, ksp = frag & 3;
            int gg = li >> 2, tt = li & 3;
            int n  = nt * 8 + gg;
            int K0 = ksp * 16;
            uint32_t b0 = packh2(m2w[(K0 + 2 * tt) * 64 + n],
                                 m2w[(K0 + 2 * tt + 1) * 64 + n]);
            uint32_t b1 = packh2(m2w[(K0 + 2 * tt + 8) * 64 + n],
                                 m2w[(K0 + 2 * tt + 9) * 64 + n]);
            sfu[frag * 64 + li] = (ull)b0 | ((ull)b1 << 32);
        }
        // edge weights: linear over E, scatter to [recv][j]
        for (int i = tid; i < Ee; i += 256) {
            int s = i / 63, t = i % 63;
            int r = t + (t >= s ? 1 : 0);
            int j = s - (s > r ? 1 : 0);
            sf[SEW + r * 64 + j] = edges[((size_t)b * Ee + i) * 2 + 1];
        }
        if (tid < 64) {
            sf[SEW + tid * 64 + 63] = 0.0f;   // pad row weight
            sf[SBIAS + tid] = m2b[tid];
        }
    }
    __syncthreads();

    // ---- prologue B: compute hb/hs for this warp's 8 nodes (exact mlp1
    // numerics), write aug[:,0:32] ----
    {
        const float* xg = inputs + (size_t)b * 2048;   // [64][32]
        float xv[8];
        #pragma unroll
        for (int q = 0; q < 8; q++)
            xv[q] = xg[(w * 8 + q) * 32 + lane];
        #pragma unroll 1
        for (int q = 0; q < 8; q++) {
            const int v = w * 8 + q;
            ull ab = sb1p[lane];
            ull as = 0ull;
            #pragma unroll
            for (int k = 0; k < 32; k++) {
                ull p = packdup(__shfl_sync(FULL, xv[q], k));
                ab = fma2(p, w1r[k * 32 + lane], ab);
                as = fma2(p, w1s[k * 32 + lane], as);
            }
            float2 fb = *reinterpret_cast<float2*>(&ab);
            float2 fs = *reinterpret_cast<float2*>(&as);
            sf[SHB + v * 64 + lane]      = fb.x;
            sf[SHB + v * 64 + lane + 32] = fb.y;
            sf[SHS + v * 68 + lane]      = fs.x;
            sf[SHS + v * 68 + lane + 32] = fs.y;
            out[OUT_AUG + ((size_t)b * 64 + v) * 96 + lane] = xv[q];
        }
    }
    __syncthreads();

    // ---- main loop (identical to R10) ----
    #pragma unroll 1
    for (int ri = 0; ri < 8; ri++) {
        const int r = w * 8 + ri;
        const int hbbase = SHB + r * 64;

        float colacc[16];
        #pragma unroll
        for (int c = 0; c < 16; c++) colacc[c] = 0.0f;

        #pragma unroll 1
        for (int mhalf = 0; mhalf < 2; mhalf++) {
            int srow[4];
            float ewm[4];
            #pragma unroll
            for (int mi = 0; mi < 4; mi++) {
                int m = mhalf * 32 + g + mi * 8;
                int s = m + (m >= r ? 1 : 0);
                if (s > 63) s = 63;            // pad row (ew=0 kills it)
                srow[mi] = s * 68;
                ewm[mi]  = sf[SEW + r * 64 + m];
            }

            float acc[2][8][4];
            #pragma unroll
            for (int mt = 0; mt < 2; mt++)
                #pragma unroll
                for (int nt = 0; nt < 8; nt++)
                    #pragma unroll
                    for (int q = 0; q < 4; q++) acc[mt][nt][q] = 0.0f;

            #pragma unroll
            for (int ksp = 0; ksp < 4; ksp++) {
                const int kL = ksp * 16 + 2 * tig;
                const int kH = kL + 8;
                const float2 hbL = *reinterpret_cast<const float2*>(&sf[hbbase + kL]);
                const float2 hbH = *reinterpret_cast<const float2*>(&sf[hbbase + kH]);
                uint32_t a[2][4];
                #pragma unroll
                for (int mt = 0; mt < 2; mt++) {
                    const int r0 = srow[mt * 2], r1 = srow[mt * 2 + 1];
                    float2 hL0 = *reinterpret_cast<const float2*>(&sf[SHS + r0 + kL]);
                    float2 hL1 = *reinterpret_cast<const float2*>(&sf[SHS + r1 + kL]);
                    float2 hH0 = *reinterpret_cast<const float2*>(&sf[SHS + r0 + kH]);
                    float2 hH1 = *reinterpret_cast<const float2*>(&sf[SHS + r1 + kH]);
                    a[mt][0] = packh2(relu(hL0.x + hbL.x), relu(hL0.y + hbL.y));
                    a[mt][1] = packh2(relu(hL1.x + hbL.x), relu(hL1.y + hbL.y));
                    a[mt][2] = packh2(relu(hH0.x + hbH.x), relu(hH0.y + hbH.y));
                    a[mt][3] = packh2(relu(hH1.x + hbH.x), relu(hH1.y + hbH.y));
                }
                #pragma unroll
                for (int nt = 0; nt < 8; nt++) {
                    ull bv = sfu[(nt * 4 + ksp) * 64 + lane];
                    uint32_t b0 = (uint32_t)bv;
                    uint32_t b1 = (uint32_t)(bv >> 32);
                    mma_f16(acc[0][nt], a[0], b0, b1);
                    mma_f16(acc[1][nt], a[1], b0, b1);
                }
            }

            #pragma unroll
            for (int nt = 0; nt < 8; nt++) {
                float bs0 = sf[SBIAS + nt * 8 + 2 * tig];
                float bs1 = sf[SBIAS + nt * 8 + 2 * tig + 1];
                #pragma unroll
                for (int mt = 0; mt < 2; mt++) {
                    float ew0 = ewm[mt * 2];
                    float ew1 = ewm[mt * 2 + 1];
                    float* c4 = acc[mt][nt];
                    colacc[nt * 2]     += relu(c4[0] + bs0) * ew0
                                        + relu(c4[2] + bs0) * ew1;
                    colacc[nt * 2 + 1] += relu(c4[1] + bs1) * ew0
                                        + relu(c4[3] + bs1) * ew1;
                }
            }
        }

        #pragma unroll
        for (int c = 0; c < 16; c++) {
            colacc[c] += __shfl_xor_sync(FULL, colacc[c], 4);
            colacc[c] += __shfl_xor_sync(FULL, colacc[c], 8);
            colacc[c] += __shfl_xor_sync(FULL, colacc[c], 16);
        }
        float v0 = 0.0f, v1 = 0.0f;
        #pragma unroll
        for (int nt = 0; nt < 8; nt++)
            if (g == nt) { v0 = colacc[nt * 2]; v1 = colacc[nt * 2 + 1]; }
        *reinterpret_cast<float2*>(
            &out[OUT_AUG + ((size_t)b * 64 + r) * 96 + 32 + g * 8 + 2 * tig]) =
            make_float2(v0, v1);
    }
}

// ============================================================================
// Kernel 2: node MLP head. Split finer: grid 1024, warp handles 4 rows
// (halves per-warp serial latency chain).
// ============================================================================
struct NodeSmem {
    ull   s1I[48][64];
    ull   s2I[32][64];
    float buf[8][4][104];
    float smu[8][64];
    float sls[8][64];
    float sb1[64], sb2[64], sbm[8], sbl[8];
};

__global__ __launch_bounds__(256) void node_kernel(
    const float* __restrict__ fc1w,
    const float* __restrict__ fc1b,
    const float* __restrict__ fc2w,
    const float* __restrict__ fc2b,
    const float* __restrict__ muw,
    const float* __restrict__ mub,
    const float* __restrict__ lsw,
    const float* __restrict__ lsb,
    float* __restrict__ out)
{
    extern __shared__ char smem_raw[];
    NodeSmem* sm = reinterpret_cast<NodeSmem*>(smem_raw);

    const int tid  = threadIdx.x;
    const int lane = tid & 31;
    const int w    = tid >> 5;

    for (int i = tid; i < 48 * 64; i += 256) {
        int kp = i >> 6, c = i & 63;
        sm->s1I[kp][c] = pack2(fc1w[(2 * kp) * 64 + c], fc1w[(2 * kp + 1) * 64 + c]);
    }
    for (int i = tid; i < 32 * 64; i += 256) {
        int kp = i >> 6, c = i & 63;
        sm->s2I[kp][c] = pack2(fc2w[(2 * kp) * 64 + c], fc2w[(2 * kp + 1) * 64 + c]);
    }
    for (int i = tid; i < 64 * 8; i += 256) {
        int k = i >> 3, a = i & 7;
        sm->smu[a][k] = muw[i];
        sm->sls[a][k] = lsw[i];
    }
    if (tid < 64) { sm->sb1[tid] = fc1b[tid]; sm->sb2[tid] = fc2b[tid]; }
    if (tid < 8)  { sm->sbm[tid] = mub[tid];  sm->sbl[tid] = lsb[tid]; }
    __syncthreads();

    const int rowbase = blockIdx.x * 32 + w * 4;

    if (lane < 24) {
        #pragma unroll
        for (int rr = 0; rr < 4; rr++) {
            const float4* src = reinterpret_cast<const float4*>(
                out + OUT_AUG + (size_t)(rowbase + rr) * 96);
            *reinterpret_cast<float4*>(&sm->buf[w][rr][lane * 4]) = src[lane];
        }
    }
    __syncwarp();

    ull alo[4], ahi[4];
    #pragma unroll
    for (int rr = 0; rr < 4; rr++) { alo[rr] = 0ull; ahi[rr] = 0ull; }
    #pragma unroll 1
    for (int kp4 = 0; kp4 < 12; kp4++) {
        ull wl[4], wh[4];
        #pragma unroll
        for (int j = 0; j < 4; j++) {
            wl[j] = sm->s1I[kp4 * 4 + j][lane];
            wh[j] = sm->s1I[kp4 * 4 + j][lane + 32];
        }
        #pragma unroll
        for (int rr = 0; rr < 4; rr++) {
            const ull2* hp = reinterpret_cast<const ull2*>(&sm->buf[w][rr][kp4 * 8]);
            ull2 ha = hp[0];
            ull2 hb2 = hp[1];
            alo[rr] = fma2(ha.x,  wl[0], alo[rr]);  ahi[rr] = fma2(ha.x,  wh[0], ahi[rr]);
            alo[rr] = fma2(ha.y,  wl[1], alo[rr]);  ahi[rr] = fma2(ha.y,  wh[1], ahi[rr]);
            alo[rr] = fma2(hb2.x, wl[2], alo[rr]);  ahi[rr] = fma2(hb2.x, wh[2], ahi[rr]);
            alo[rr] = fma2(hb2.y, wl[3], alo[rr]);  ahi[rr] = fma2(hb2.y, wh[3], ahi[rr]);
        }
    }
    __syncwarp();
    {
        const float b0 = sm->sb1[lane], b1 = sm->sb1[lane + 32];
        #pragma unroll
        for (int rr = 0; rr < 4; rr++) {
            float2 pl = *reinterpret_cast<float2*>(&alo[rr]);
            float2 ph = *reinterpret_cast<float2*>(&ahi[rr]);
            sm->buf[w][rr][lane]      = relu(pl.x + pl.y + b0);
            sm->buf[w][rr][lane + 32] = relu(ph.x + ph.y + b1);
        }
    }
    __syncwarp();

    #pragma unroll
    for (int rr = 0; rr < 4; rr++) { alo[rr] = 0ull; ahi[rr] = 0ull; }
    #pragma unroll 1
    for (int kp4 = 0; kp4 < 8; kp4++) {
        ull wl[4], wh[4];
        #pragma unroll
        for (int j = 0; j < 4; j++) {
            wl[j] = sm->s2I[kp4 * 4 + j][lane];
            wh[j] = sm->s2I[kp4 * 4 + j][lane + 32];
        }
        #pragma unroll
        for (int rr = 0; rr < 4; rr++) {
            const ull2* hp = reinterpret_cast<const ull2*>(&sm->buf[w][rr][kp4 * 8]);
            ull2 ha = hp[0];
            ull2 hb2 = hp[1];
            alo[rr] = fma2(ha.x,  wl[0], alo[rr]);  ahi[rr] = fma2(ha.x,  wh[0], ahi[rr]);
            alo[rr] = fma2(ha.y,  wl[1], alo[rr]);  ahi[rr] = fma2(ha.y,  wh[1], ahi[rr]);
            alo[rr] = fma2(hb2.x, wl[2], alo[rr]);  ahi[rr] = fma2(hb2.x, wh[2], ahi[rr]);
            alo[rr] = fma2(hb2.y, wl[3], alo[rr]);  ahi[rr] = fma2(hb2.y, wh[3], ahi[rr]);
        }
    }
    __syncwarp();
    {
        const float b0 = sm->sb2[lane], b1 = sm->sb2[lane + 32];
        #pragma unroll
        for (int rr = 0; rr < 4; rr++) {
            float2 pl = *reinterpret_cast<float2*>(&alo[rr]);
            float2 ph = *reinterpret_cast<float2*>(&ahi[rr]);
            sm->buf[w][rr][lane]      = relu(pl.x + pl.y + b0);
            sm->buf[w][rr][lane + 32] = relu(ph.x + ph.y + b1);
        }
    }
    __syncwarp();

    const int a   = lane >> 2;
    const int seg = lane & 3;
    #pragma unroll 1
    for (int rr = 0; rr < 4; rr++) {
        const int row = rowbase + rr;
        const float* trow = &sm->buf[w][rr][0];
        float pm = 0.f, pl = 0.f;
        #pragma unroll
        for (int j4 = 0; j4 < 4; j4++) {
            int k = seg * 16 + j4 * 4;
            float4 tv = *reinterpret_cast<const float4*>(trow + k);
            float4 mv = *reinterpret_cast<const float4*>(&sm->smu[a][k]);
            float4 lv = *reinterpret_cast<const float4*>(&sm->sls[a][k]);
            pm = fmaf(tv.x, mv.x, pm); pm = fmaf(tv.y, mv.y, pm);
            pm = fmaf(tv.z, mv.z, pm); pm = fmaf(tv.w, mv.w, pm);
            pl = fmaf(tv.x, lv.x, pl); pl = fmaf(tv.y, lv.y, pl);
            pl = fmaf(tv.z, lv.z, pl); pl = fmaf(tv.w, lv.w, pl);
        }
        pm += __shfl_xor_sync(FULL, pm, 1); pm += __shfl_xor_sync(FULL, pm, 2);
        pl += __shfl_xor_sync(FULL, pl, 1); pl += __shfl_xor_sync(FULL, pl, 2);

        float mu = pm + sm->sbm[a];
        float ls = fminf(fmaxf(pl + sm->sbl[a], -3.0f), 1.0f);
        float x  = -2.0f * mu;
        float sp = fmaxf(x, 0.0f) + log1pf(expf(-fabsf(x)));
        float c  = -ls - HALF_LOG_2PI_F - 2.0f * (LOG2_F - mu - sp);

        if (seg == 0) out[OUT_TANH + (size_t)row * Aa + a] = tanhf(mu);

        float val = (seg == 0) ? c : 0.f;
        val += __shfl_xor_sync(FULL, val, 4);
        val += __shfl_xor_sync(FULL, val, 8);
        val += __shfl_xor_sync(FULL, val, 16);
        if (lane == 0) out[OUT_LOGP + row] = val;
    }
}

extern "C" void kernel_launch(void* const* d_in, const int* in_sizes, int n_in,
                              void* d_out, int out_size) {
    (void)in_sizes; (void)n_in; (void)out_size;
    const float* inputs = (const float*)d_in[0];
    const float* edges  = (const float*)d_in[1];
    const float* m1w    = (const float*)d_in[2];
    const float* m1b    = (const float*)d_in[3];
    const float* m2w    = (const float*)d_in[4];
    const float* m2b    = (const float*)d_in[5];
    const float* fc1w   = (const float*)d_in[6];
    const float* fc1b   = (const float*)d_in[7];
    const float* fc2w   = (const float*)d_in[8];
    const float* fc2b   = (const float*)d_in[9];
    const float* muw    = (const float*)d_in[10];
    const float* mub    = (const float*)d_in[11];
    const float* lsw    = (const float*)d_in[12];
    const float* lsb    = (const float*)d_in[13];
    float* out = (float*)d_out;

    cudaFuncSetAttribute(edge_kernel,
                         cudaFuncAttributeMaxDynamicSharedMemorySize, EDGE_SMEM_B);
    cudaFuncSetAttribute(node_kernel,
                         cudaFuncAttributeMaxDynamicSharedMemorySize,
                         (int)sizeof(NodeSmem));

    edge_kernel<<<512, 256, EDGE_SMEM_B>>>(
        inputs, edges, m1w, m1b, m2w, m2b, out);
    node_kernel<<<1024, 256, sizeof(NodeSmem)>>>(
        fc1w, fc1b, fc2w, fc2b, muw, mub, lsw, lsb, out);
}

// round 12
// speedup vs baseline: 1.1477x; 1.1477x over previous
#include <cuda_runtime.h>
#include <cstdint>

#define FULL 0xffffffffu
typedef unsigned long long ull;
typedef ulonglong2 ull2;

// Problem dims
constexpr int Bb = 512;
constexpr int Vv = 64;
constexpr int Aa = 8;
constexpr int Ee = Vv * (Vv - 1);   // 4032

// Output layout: [tanh_mu B*V*A][logp B*V][aug B*V*96]
constexpr size_t OUT_TANH = 0;
constexpr size_t OUT_LOGP = (size_t)Bb * Vv * Aa;          // 262144
constexpr size_t OUT_AUG  = OUT_LOGP + (size_t)Bb * Vv;    // 294912

__device__ __forceinline__ float relu(float x) { return fmaxf(x, 0.0f); }

constexpr float HALF_LOG_2PI_F = 0.91893853320467274f;
constexpr float LOG2_F         = 0.69314718055994531f;

// ---- packed fp32x2 helpers ----
__device__ __forceinline__ ull fma2(ull a, ull b, ull c) {
    ull d;
    asm("fma.rn.f32x2 %0, %1, %2, %3;" : "=l"(d) : "l"(a), "l"(b), "l"(c));
    return d;
}
__device__ __forceinline__ ull packdup(float x) {
    ull d;
    asm("mov.b64 %0, {%1, %1};" : "=l"(d) : "f"(x));
    return d;
}
__device__ __forceinline__ ull pack2(float lo, float hi) {
    ull d;
    asm("mov.b64 %0, {%1, %2};" : "=l"(d) : "f"(lo), "f"(hi));
    return d;
}
// pack two fp32 into half2: lo -> bits[15:0], hi -> bits[31:16]
__device__ __forceinline__ uint32_t packh2(float lo, float hi) {
    uint32_t d;
    asm("cvt.rn.f16x2.f32 %0, %1, %2;" : "=r"(d) : "f"(hi), "f"(lo));
    return d;
}

// m16n8k16 f16 mma, f32 accumulate (sm_80+ path, legal on plain sm_103)
__device__ __forceinline__ void mma_f16(float c[4], const uint32_t a[4],
                                        uint32_t b0, uint32_t b1) {
    asm volatile(
        "mma.sync.aligned.m16n8k16.row.col.f32.f16.f16.f32 "
        "{%0,%1,%2,%3}, {%4,%5,%6,%7}, {%8,%9}, {%0,%1,%2,%3};"
        : "+f"(c[0]), "+f"(c[1]), "+f"(c[2]), "+f"(c[3])
        : "r"(a[0]), "r"(a[1]), "r"(a[2]), "r"(a[3]), "r"(b0), "r"(b1));
}

// Scratch for MLP1 halves + prepacked node weights
__device__ float g_hb[(size_t)Bb * Vv * 64];
__device__ float g_hs[(size_t)Bb * Vv * 64];
__device__ ull   g_w1I[48 * 64];   // fc1w interleaved [kpair][c]
__device__ ull   g_w2I[32 * 64];   // fc2w interleaved

// ============================================================================
// Kernel 0: MLP1 halves per (b,v); copies inputs into aug[:,0:32].
// Block 0 additionally prepacks the node weights into g_w1I/g_w2I.
// ============================================================================
__global__ __launch_bounds__(256) void mlp1_kernel(
    const float* __restrict__ inputs,   // [B*V, 32]
    const float* __restrict__ m1w,      // [64,64]
    const float* __restrict__ m1b,      // [64]
    const float* __restrict__ fc1w,     // [96,64]
    const float* __restrict__ fc2w,     // [64,64]
    float* __restrict__ out)
{
    __shared__ ull wr[32][32];
    __shared__ ull ws[32][32];
    __shared__ ull sbb[32];

    const int tid = threadIdx.x;
    if (blockIdx.x == 0) {
        for (int i = tid; i < 48 * 64; i += 256) {
            int kp = i >> 6, c = i & 63;
            g_w1I[i] = pack2(fc1w[(2 * kp) * 64 + c], fc1w[(2 * kp + 1) * 64 + c]);
        }
        for (int i = tid; i < 32 * 64; i += 256) {
            int kp = i >> 6, c = i & 63;
            g_w2I[i] = pack2(fc2w[(2 * kp) * 64 + c], fc2w[(2 * kp + 1) * 64 + c]);
        }
    }
    for (int i = tid; i < 32 * 32; i += 256) {
        int k = i >> 5, c = i & 31;
        wr[k][c] = pack2(m1w[k * 64 + c],        m1w[k * 64 + c + 32]);
        ws[k][c] = pack2(m1w[(32 + k) * 64 + c], m1w[(32 + k) * 64 + c + 32]);
    }
    if (tid < 32) sbb[tid] = pack2(m1b[tid], m1b[tid + 32]);
    __syncthreads();

    const int lane = tid & 31;
    const int w    = tid >> 5;
    const size_t baserow = (size_t)blockIdx.x * 32 + w * 4;

    float xv[4];
    ull ab[4], as2[4];
    #pragma unroll
    for (int q = 0; q < 4; q++) {
        xv[q]  = inputs[(baserow + q) * 32 + lane];
        ab[q]  = sbb[lane];
        as2[q] = 0ull;
    }
    #pragma unroll
    for (int k = 0; k < 32; k++) {
        ull wrk = wr[k][lane];
        ull wsk = ws[k][lane];
        #pragma unroll
        for (int q = 0; q < 4; q++) {
            ull p = packdup(__shfl_sync(FULL, xv[q], k));
            ab[q]  = fma2(p, wrk, ab[q]);
            as2[q] = fma2(p, wsk, as2[q]);
        }
    }
    #pragma unroll
    for (int q = 0; q < 4; q++) {
        size_t row = baserow + q;
        float2 fb = *reinterpret_cast<float2*>(&ab[q]);
        float2 fs = *reinterpret_cast<float2*>(&as2[q]);
        g_hb[row * 64 + lane]      = fb.x;
        g_hb[row * 64 + lane + 32] = fb.y;
        g_hs[row * 64 + lane]      = fs.x;
        g_hs[row * 64 + lane + 32] = fs.y;
        out[OUT_AUG + row * 96 + lane] = xv[q];   // aug[:, 0:32]
    }
}

// ============================================================================
// Kernel 1: edge MLP2 via fp16 m16n8k16 mma.sync + fp32 aggregation.
// EXACT R10 version (best measured edge).
// ============================================================================
constexpr int SHS   = 0;                 // hs [64][68] padded (floats)
constexpr int SHB   = SHS + 64 * 68;     // hb [64][64]
constexpr int SBF   = SHB + 64 * 64;     // B frags: 32 frags x 64 lanes x ull
constexpr int SEW   = SBF + 32 * 64 * 2; // ew [64][64]
constexpr int SBIAS = SEW + 64 * 64;     // [64]
constexpr int EDGE_SMEM_F = SBIAS + 64;
constexpr int EDGE_SMEM_B = EDGE_SMEM_F * 4;

__global__ __launch_bounds__(256, 2) void edge_kernel(
    const float* __restrict__ edges,    // [B,E,2]
    const float* __restrict__ m2w,      // [64,64]
    const float* __restrict__ m2b,      // [64]
    float* __restrict__ out)
{
    extern __shared__ float sf[];
    ull* sfu = reinterpret_cast<ull*>(&sf[SBF]);

    const int b    = blockIdx.x;
    const int tid  = threadIdx.x;
    const int lane = tid & 31;
    const int w    = tid >> 5;
    const int g    = lane >> 2;   // group id (rows / n-cols)
    const int tig  = lane & 3;    // thread in group

    // ---- prologue ----
    {
        const float* hs_g = g_hs + (size_t)b * 4096;
        const float* hb_g = g_hb + (size_t)b * 4096;
        for (int i = tid; i < 4096; i += 256) {
            sf[SHS + (i >> 6) * 68 + (i & 63)] = hs_g[i];
            sf[SHB + i] = hb_g[i];
        }
        // B fragments (fragment-major, fp16)
        for (int i = tid; i < 2048; i += 256) {
            int frag = i >> 6, li = i & 63;
            int nt = frag >> 2, ksp = frag & 3;
            int gg = li >> 2, tt = li & 3;
            int n  = nt * 8 + gg;
            int K0 = ksp * 16;
            uint32_t b0 = packh2(m2w[(K0 + 2 * tt) * 64 + n],
                                 m2w[(K0 + 2 * tt + 1) * 64 + n]);
            uint32_t b1 = packh2(m2w[(K0 + 2 * tt + 8) * 64 + n],
                                 m2w[(K0 + 2 * tt + 9) * 64 + n]);
            sfu[frag * 64 + li] = (ull)b0 | ((ull)b1 << 32);
        }
        // edge weights: linear over E, scatter to [recv][j]
        for (int i = tid; i < Ee; i += 256) {
            int s = i / 63, t = i % 63;
            int r = t + (t >= s ? 1 : 0);
            int j = s - (s > r ? 1 : 0);
            sf[SEW + r * 64 + j] = edges[((size_t)b * Ee + i) * 2 + 1];
        }
        if (tid < 64) {
            sf[SEW + tid * 64 + 63] = 0.0f;   // pad row weight
            sf[SBIAS + tid] = m2b[tid];
        }
    }
    __syncthreads();

    #pragma unroll 1
    for (int ri = 0; ri < 8; ri++) {
        const int r = w * 8 + ri;
        const int hbbase = SHB + r * 64;

        float colacc[16];
        #pragma unroll
        for (int c = 0; c < 16; c++) colacc[c] = 0.0f;

        #pragma unroll 1
        for (int mhalf = 0; mhalf < 2; mhalf++) {
            int srow[4];
            float ewm[4];
            #pragma unroll
            for (int mi = 0; mi < 4; mi++) {
                int m = mhalf * 32 + g + mi * 8;
                int s = m + (m >= r ? 1 : 0);
                if (s > 63) s = 63;            // pad row (ew=0 kills it)
                srow[mi] = s * 68;
                ewm[mi]  = sf[SEW + r * 64 + m];
            }

            float acc[2][8][4];
            #pragma unroll
            for (int mt = 0; mt < 2; mt++)
                #pragma unroll
                for (int nt = 0; nt < 8; nt++)
                    #pragma unroll
                    for (int q = 0; q < 4; q++) acc[mt][nt][q] = 0.0f;

            #pragma unroll
            for (int ksp = 0; ksp < 4; ksp++) {
                const int kL = ksp * 16 + 2 * tig;
                const int kH = kL + 8;
                const float2 hbL = *reinterpret_cast<const float2*>(&sf[hbbase + kL]);
                const float2 hbH = *reinterpret_cast<const float2*>(&sf[hbbase + kH]);
                uint32_t a[2][4];
                #pragma unroll
                for (int mt = 0; mt < 2; mt++) {
                    const int r0 = srow[mt * 2], r1 = srow[mt * 2 + 1];
                    float2 hL0 = *reinterpret_cast<const float2*>(&sf[SHS + r0 + kL]);
                    float2 hL1 = *reinterpret_cast<const float2*>(&sf[SHS + r1 + kL]);
                    float2 hH0 = *reinterpret_cast<const float2*>(&sf[SHS + r0 + kH]);
                    float2 hH1 = *reinterpret_cast<const float2*>(&sf[SHS + r1 + kH]);
                    a[mt][0] = packh2(relu(hL0.x + hbL.x), relu(hL0.y + hbL.y));
                    a[mt][1] = packh2(relu(hL1.x + hbL.x), relu(hL1.y + hbL.y));
                    a[mt][2] = packh2(relu(hH0.x + hbH.x), relu(hH0.y + hbH.y));
                    a[mt][3] = packh2(relu(hH1.x + hbH.x), relu(hH1.y + hbH.y));
                }
                #pragma unroll
                for (int nt = 0; nt < 8; nt++) {
                    ull bv = sfu[(nt * 4 + ksp) * 64 + lane];
                    uint32_t b0 = (uint32_t)bv;
                    uint32_t b1 = (uint32_t)(bv >> 32);
                    mma_f16(acc[0][nt], a[0], b0, b1);
                    mma_f16(acc[1][nt], a[1], b0, b1);
                }
            }

            #pragma unroll
            for (int nt = 0; nt < 8; nt++) {
                float bs0 = sf[SBIAS + nt * 8 + 2 * tig];
                float bs1 = sf[SBIAS + nt * 8 + 2 * tig + 1];
                #pragma unroll
                for (int mt = 0; mt < 2; mt++) {
                    float ew0 = ewm[mt * 2];
                    float ew1 = ewm[mt * 2 + 1];
                    float* c4 = acc[mt][nt];
                    colacc[nt * 2]     += relu(c4[0] + bs0) * ew0
                                        + relu(c4[2] + bs0) * ew1;
                    colacc[nt * 2 + 1] += relu(c4[1] + bs1) * ew0
                                        + relu(c4[3] + bs1) * ew1;
                }
            }
        }

        #pragma unroll
        for (int c = 0; c < 16; c++) {
            colacc[c] += __shfl_xor_sync(FULL, colacc[c], 4);
            colacc[c] += __shfl_xor_sync(FULL, colacc[c], 8);
            colacc[c] += __shfl_xor_sync(FULL, colacc[c], 16);
        }
        float v0 = 0.0f, v1 = 0.0f;
        #pragma unroll
        for (int nt = 0; nt < 8; nt++)
            if (g == nt) { v0 = colacc[nt * 2]; v1 = colacc[nt * 2 + 1]; }
        *reinterpret_cast<float2*>(
            &out[OUT_AUG + ((size_t)b * 64 + r) * 96 + 32 + g * 8 + 2 * tig]) =
            make_float2(v0, v1);
    }
}

// ============================================================================
// Kernel 2: node MLP head. R10 structure (8 rows/warp, grid 512), but fc1/fc2
// weights read via coalesced LDG from prepacked globals (L1-resident) instead
// of smem staging: smem ~32KB -> 4 blocks/SM, 32 warps, single wave.
// ============================================================================
struct NodeSmem {
    float buf[8][8][104];
    float smu[8][64];
    float sls[8][64];
    float sb1[64], sb2[64], sbm[8], sbl[8];
};

__global__ __launch_bounds__(256, 4) void node_kernel(
    const float* __restrict__ fc1b,
    const float* __restrict__ fc2b,
    const float* __restrict__ muw,
    const float* __restrict__ mub,
    const float* __restrict__ lsw,
    const float* __restrict__ lsb,
    float* __restrict__ out)
{
    extern __shared__ char smem_raw[];
    NodeSmem* sm = reinterpret_cast<NodeSmem*>(smem_raw);

    const int tid  = threadIdx.x;
    const int lane = tid & 31;
    const int w    = tid >> 5;

    for (int i = tid; i < 64 * 8; i += 256) {
        int k = i >> 3, a = i & 7;
        sm->smu[a][k] = muw[i];
        sm->sls[a][k] = lsw[i];
    }
    if (tid < 64) { sm->sb1[tid] = fc1b[tid]; sm->sb2[tid] = fc2b[tid]; }
    if (tid < 8)  { sm->sbm[tid] = mub[tid];  sm->sbl[tid] = lsb[tid]; }
    __syncthreads();

    const int rowbase = blockIdx.x * 64 + w * 8;

    if (lane < 24) {
        #pragma unroll
        for (int rr = 0; rr < 8; rr++) {
            const float4* src = reinterpret_cast<const float4*>(
                out + OUT_AUG + (size_t)(rowbase + rr) * 96);
            *reinterpret_cast<float4*>(&sm->buf[w][rr][lane * 4]) = src[lane];
        }
    }
    __syncwarp();

    ull alo[8], ahi[8];
    #pragma unroll
    for (int rr = 0; rr < 8; rr++) { alo[rr] = 0ull; ahi[rr] = 0ull; }
    #pragma unroll 1
    for (int kp4 = 0; kp4 < 12; kp4++) {
        ull wl[4], wh[4];
        #pragma unroll
        for (int j = 0; j < 4; j++) {
            wl[j] = __ldg(&g_w1I[(kp4 * 4 + j) * 64 + lane]);
            wh[j] = __ldg(&g_w1I[(kp4 * 4 + j) * 64 + lane + 32]);
        }
        #pragma unroll
        for (int rr = 0; rr < 8; rr++) {
            const ull2* hp = reinterpret_cast<const ull2*>(&sm->buf[w][rr][kp4 * 8]);
            ull2 ha = hp[0];
            ull2 hb2 = hp[1];
            alo[rr] = fma2(ha.x,  wl[0], alo[rr]);  ahi[rr] = fma2(ha.x,  wh[0], ahi[rr]);
            alo[rr] = fma2(ha.y,  wl[1], alo[rr]);  ahi[rr] = fma2(ha.y,  wh[1], ahi[rr]);
            alo[rr] = fma2(hb2.x, wl[2], alo[rr]);  ahi[rr] = fma2(hb2.x, wh[2], ahi[rr]);
            alo[rr] = fma2(hb2.y, wl[3], alo[rr]);  ahi[rr] = fma2(hb2.y, wh[3], ahi[rr]);
        }
    }
    __syncwarp();
    {
        const float b0 = sm->sb1[lane], b1 = sm->sb1[lane + 32];
        #pragma unroll
        for (int rr = 0; rr < 8; rr++) {
            float2 pl = *reinterpret_cast<float2*>(&alo[rr]);
            float2 ph = *reinterpret_cast<float2*>(&ahi[rr]);
            sm->buf[w][rr][lane]      = relu(pl.x + pl.y + b0);
            sm->buf[w][rr][lane + 32] = relu(ph.x + ph.y + b1);
        }
    }
    __syncwarp();

    #pragma unroll
    for (int rr = 0; rr < 8; rr++) { alo[rr] = 0ull; ahi[rr] = 0ull; }
    #pragma unroll 1
    for (int kp4 = 0; kp4 < 8; kp4++) {
        ull wl[4], wh[4];
        #pragma unroll
        for (int j = 0; j < 4; j++) {
            wl[j] = __ldg(&g_w2I[(kp4 * 4 + j) * 64 + lane]);
            wh[j] = __ldg(&g_w2I[(kp4 * 4 + j) * 64 + lane + 32]);
        }
        #pragma unroll
        for (int rr = 0; rr < 8; rr++) {
            const ull2* hp = reinterpret_cast<const ull2*>(&sm->buf[w][rr][kp4 * 8]);
            ull2 ha = hp[0];
            ull2 hb2 = hp[1];
            alo[rr] = fma2(ha.x,  wl[0], alo[rr]);  ahi[rr] = fma2(ha.x,  wh[0], ahi[rr]);
            alo[rr] = fma2(ha.y,  wl[1], alo[rr]);  ahi[rr] = fma2(ha.y,  wh[1], ahi[rr]);
            alo[rr] = fma2(hb2.x, wl[2], alo[rr]);  ahi[rr] = fma2(hb2.x, wh[2], ahi[rr]);
            alo[rr] = fma2(hb2.y, wl[3], alo[rr]);  ahi[rr] = fma2(hb2.y, wh[3], ahi[rr]);
        }
    }
    __syncwarp();
    {
        const float b0 = sm->sb2[lane], b1 = sm->sb2[lane + 32];
        #pragma unroll
        for (int rr = 0; rr < 8; rr++) {
            float2 pl = *reinterpret_cast<float2*>(&alo[rr]);
            float2 ph = *reinterpret_cast<float2*>(&ahi[rr]);
            sm->buf[w][rr][lane]      = relu(pl.x + pl.y + b0);
            sm->buf[w][rr][lane + 32] = relu(ph.x + ph.y + b1);
        }
    }
    __syncwarp();

    const int a   = lane >> 2;
    const int seg = lane & 3;
    #pragma unroll 1
    for (int rr = 0; rr < 8; rr++) {
        const int row = rowbase + rr;
        const float* trow = &sm->buf[w][rr][0];
        float pm = 0.f, pl = 0.f;
        #pragma unroll
        for (int j4 = 0; j4 < 4; j4++) {
            int k = seg * 16 + j4 * 4;
            float4 tv = *reinterpret_cast<const float4*>(trow + k);
            float4 mv = *reinterpret_cast<const float4*>(&sm->smu[a][k]);
            float4 lv = *reinterpret_cast<const float4*>(&sm->sls[a][k]);
            pm = fmaf(tv.x, mv.x, pm); pm = fmaf(tv.y, mv.y, pm);
            pm = fmaf(tv.z, mv.z, pm); pm = fmaf(tv.w, mv.w, pm);
            pl = fmaf(tv.x, lv.x, pl); pl = fmaf(tv.y, lv.y, pl);
            pl = fmaf(tv.z, lv.z, pl); pl = fmaf(tv.w, lv.w, pl);
        }
        pm += __shfl_xor_sync(FULL, pm, 1); pm += __shfl_xor_sync(FULL, pm, 2);
        pl += __shfl_xor_sync(FULL, pl, 1); pl += __shfl_xor_sync(FULL, pl, 2);

        float mu = pm + sm->sbm[a];
        float ls = fminf(fmaxf(pl + sm->sbl[a], -3.0f), 1.0f);
        float x  = -2.0f * mu;
        float sp = fmaxf(x, 0.0f) + log1pf(expf(-fabsf(x)));
        float c  = -ls - HALF_LOG_2PI_F - 2.0f * (LOG2_F - mu - sp);

        if (seg == 0) out[OUT_TANH + (size_t)row * Aa + a] = tanhf(mu);

        float val = (seg == 0) ? c : 0.f;
        val += __shfl_xor_sync(FULL, val, 4);
        val += __shfl_xor_sync(FULL, val, 8);
        val += __shfl_xor_sync(FULL, val, 16);
        if (lane == 0) out[OUT_LOGP + row] = val;
    }
}

extern "C" void kernel_launch(void* const* d_in, const int* in_sizes, int n_in,
                              void* d_out, int out_size) {
    (void)in_sizes; (void)n_in; (void)out_size;
    const float* inputs = (const float*)d_in[0];
    const float* edges  = (const float*)d_in[1];
    const float* m1w    = (const float*)d_in[2];
    const float* m1b    = (const float*)d_in[3];
    const float* m2w    = (const float*)d_in[4];
    const float* m2b    = (const float*)d_in[5];
    const float* fc1w   = (const float*)d_in[6];
    const float* fc1b   = (const float*)d_in[7];
    const float* fc2w   = (const float*)d_in[8];
    const float* fc2b   = (const float*)d_in[9];
    const float* muw    = (const float*)d_in[10];
    const float* mub    = (const float*)d_in[11];
    const float* lsw    = (const float*)d_in[12];
    const float* lsb    = (const float*)d_in[13];
    float* out = (float*)d_out;

    cudaFuncSetAttribute(edge_kernel,
                         cudaFuncAttributeMaxDynamicSharedMemorySize, EDGE_SMEM_B);
    cudaFuncSetAttribute(node_kernel,
                         cudaFuncAttributeMaxDynamicSharedMemorySize,
                         (int)sizeof(NodeSmem));

    mlp1_kernel<<<1024, 256>>>(inputs, m1w, m1b, fc1w, fc2w, out);
    edge_kernel<<<512, 256, EDGE_SMEM_B>>>(edges, m2w, m2b, out);
    node_kernel<<<512, 256, sizeof(NodeSmem)>>>(
        fc1b, fc2b, muw, mub, lsw, lsb, out);
}

// round 13
// speedup vs baseline: 1.1515x; 1.0033x over previous
#include <cuda_runtime.h>
#include <cstdint>

#define FULL 0xffffffffu
typedef unsigned long long ull;
typedef ulonglong2 ull2;

// Problem dims
constexpr int Bb = 512;
constexpr int Vv = 64;
constexpr int Aa = 8;
constexpr int Ee = Vv * (Vv - 1);   // 4032

// Output layout: [tanh_mu B*V*A][logp B*V][aug B*V*96]
constexpr size_t OUT_TANH = 0;
constexpr size_t OUT_LOGP = (size_t)Bb * Vv * Aa;          // 262144
constexpr size_t OUT_AUG  = OUT_LOGP + (size_t)Bb * Vv;    // 294912

__device__ __forceinline__ float relu(float x) { return fmaxf(x, 0.0f); }

constexpr float HALF_LOG_2PI_F = 0.91893853320467274f;
constexpr float LOG2_F         = 0.69314718055994531f;

// ---- packed fp32x2 helpers ----
__device__ __forceinline__ ull fma2(ull a, ull b, ull c) {
    ull d;
    asm("fma.rn.f32x2 %0, %1, %2, %3;" : "=l"(d) : "l"(a), "l"(b), "l"(c));
    return d;
}
__device__ __forceinline__ ull packdup(float x) {
    ull d;
    asm("mov.b64 %0, {%1, %1};" : "=l"(d) : "f"(x));
    return d;
}
__device__ __forceinline__ ull pack2(float lo, float hi) {
    ull d;
    asm("mov.b64 %0, {%1, %2};" : "=l"(d) : "f"(lo), "f"(hi));
    return d;
}
// pack two fp32 into half2: lo -> bits[15:0], hi -> bits[31:16]
__device__ __forceinline__ uint32_t packh2(float lo, float hi) {
    uint32_t d;
    asm("cvt.rn.f16x2.f32 %0, %1, %2;" : "=r"(d) : "f"(hi), "f"(lo));
    return d;
}

// m16n8k16 f16 mma, f32 accumulate (sm_80+ path, legal on plain sm_103)
__device__ __forceinline__ void mma_f16(float c[4], const uint32_t a[4],
                                        uint32_t b0, uint32_t b1) {
    asm volatile(
        "mma.sync.aligned.m16n8k16.row.col.f32.f16.f16.f32 "
        "{%0,%1,%2,%3}, {%4,%5,%6,%7}, {%8,%9}, {%0,%1,%2,%3};"
        : "+f"(c[0]), "+f"(c[1]), "+f"(c[2]), "+f"(c[3])
        : "r"(a[0]), "r"(a[1]), "r"(a[2]), "r"(a[3]), "r"(b0), "r"(b1));
}

// Scratch for MLP1 halves + prepacked node weights
__device__ float g_hb[(size_t)Bb * Vv * 64];
__device__ float g_hs[(size_t)Bb * Vv * 64];
__device__ ull   g_w1I[48 * 64];   // fc1w interleaved [kpair][c]
__device__ ull   g_w2I[32 * 64];   // fc2w interleaved

// ============================================================================
// Kernel 0: MLP1 halves per (b,v); copies inputs into aug[:,0:32].
// Block 0 additionally prepacks the node weights into g_w1I/g_w2I.
// ============================================================================
__global__ __launch_bounds__(256) void mlp1_kernel(
    const float* __restrict__ inputs,   // [B*V, 32]
    const float* __restrict__ m1w,      // [64,64]
    const float* __restrict__ m1b,      // [64]
    const float* __restrict__ fc1w,     // [96,64]
    const float* __restrict__ fc2w,     // [64,64]
    float* __restrict__ out)
{
    __shared__ ull wr[32][32];
    __shared__ ull ws[32][32];
    __shared__ ull sbb[32];

    const int tid = threadIdx.x;
    if (blockIdx.x == 0) {
        for (int i = tid; i < 48 * 64; i += 256) {
            int kp = i >> 6, c = i & 63;
            g_w1I[i] = pack2(fc1w[(2 * kp) * 64 + c], fc1w[(2 * kp + 1) * 64 + c]);
        }
        for (int i = tid; i < 32 * 64; i += 256) {
            int kp = i >> 6, c = i & 63;
            g_w2I[i] = pack2(fc2w[(2 * kp) * 64 + c], fc2w[(2 * kp + 1) * 64 + c]);
        }
    }
    for (int i = tid; i < 32 * 32; i += 256) {
        int k = i >> 5, c = i & 31;
        wr[k][c] = pack2(m1w[k * 64 + c],        m1w[k * 64 + c + 32]);
        ws[k][c] = pack2(m1w[(32 + k) * 64 + c], m1w[(32 + k) * 64 + c + 32]);
    }
    if (tid < 32) sbb[tid] = pack2(m1b[tid], m1b[tid + 32]);
    __syncthreads();

    const int lane = tid & 31;
    const int w    = tid >> 5;
    const size_t baserow = (size_t)blockIdx.x * 32 + w * 4;

    float xv[4];
    ull ab[4], as2[4];
    #pragma unroll
    for (int q = 0; q < 4; q++) {
        xv[q]  = inputs[(baserow + q) * 32 + lane];
        ab[q]  = sbb[lane];
        as2[q] = 0ull;
    }
    #pragma unroll
    for (int k = 0; k < 32; k++) {
        ull wrk = wr[k][lane];
        ull wsk = ws[k][lane];
        #pragma unroll
        for (int q = 0; q < 4; q++) {
            ull p = packdup(__shfl_sync(FULL, xv[q], k));
            ab[q]  = fma2(p, wrk, ab[q]);
            as2[q] = fma2(p, wsk, as2[q]);
        }
    }
    #pragma unroll
    for (int q = 0; q < 4; q++) {
        size_t row = baserow + q;
        float2 fb = *reinterpret_cast<float2*>(&ab[q]);
        float2 fs = *reinterpret_cast<float2*>(&as2[q]);
        g_hb[row * 64 + lane]      = fb.x;
        g_hb[row * 64 + lane + 32] = fb.y;
        g_hs[row * 64 + lane]      = fs.x;
        g_hs[row * 64 + lane + 32] = fs.y;
        out[OUT_AUG + row * 96 + lane] = xv[q];   // aug[:, 0:32]
    }
}

// ============================================================================
// Kernel 1: FUSED edge MLP2 (fp16 mma) + aggregation + node MLP head.
// Block = batch; warp w owns receivers/rows w*8..w*8+7. The agg for those
// rows lands in a warp-private smem buf, then the node head runs in-warp
// (identical numerics to the standalone node kernel).
// ============================================================================
constexpr int SHS   = 0;                   // hs [64][68] padded (floats)
constexpr int SHB   = SHS + 64 * 68;       // hb [64][64]
constexpr int SBF   = SHB + 64 * 64;       // B frags: 32x64 ull (4096 floats)
constexpr int SEW   = SBF + 32 * 64 * 2;   // ew [64][64]
constexpr int SBIAS = SEW + 64 * 64;       // m2b [64]
constexpr int SBUF  = SBIAS + 64;          // node buf [8][8][104]
constexpr int SMU   = SBUF + 8 * 8 * 104;  // muw^T [8][64]
constexpr int SLS   = SMU + 512;           // lsw^T [8][64]
constexpr int SB1   = SLS + 512;           // fc1b [64]
constexpr int SB2   = SB1 + 64;            // fc2b [64]
constexpr int SBM   = SB2 + 64;            // mub [8]
constexpr int SBL   = SBM + 8;             // lsb [8]
constexpr int EDGE_SMEM_F = SBL + 8;
constexpr int EDGE_SMEM_B = EDGE_SMEM_F * 4;   // ~98.1 KB

__global__ __launch_bounds__(256, 2) void edge_kernel(
    const float* __restrict__ inputs,   // [B,V,32]
    const float* __restrict__ edges,    // [B,E,2]
    const float* __restrict__ m2w,      // [64,64]
    const float* __restrict__ m2b,      // [64]
    const float* __restrict__ fc1b,
    const float* __restrict__ fc2b,
    const float* __restrict__ muw,      // [64,8]
    const float* __restrict__ mub,
    const float* __restrict__ lsw,      // [64,8]
    const float* __restrict__ lsb,
    float* __restrict__ out)
{
    extern __shared__ float sf[];
    ull* sfu = reinterpret_cast<ull*>(&sf[SBF]);

    const int b    = blockIdx.x;
    const int tid  = threadIdx.x;
    const int lane = tid & 31;
    const int w    = tid >> 5;
    const int g    = lane >> 2;   // group id (rows / n-cols)
    const int tig  = lane & 3;    // thread in group

    // ---- prologue ----
    {
        const float* hs_g = g_hs + (size_t)b * 4096;
        const float* hb_g = g_hb + (size_t)b * 4096;
        for (int i = tid; i < 4096; i += 256) {
            sf[SHS + (i >> 6) * 68 + (i & 63)] = hs_g[i];
            sf[SHB + i] = hb_g[i];
        }
        // B fragments (fragment-major, fp16)
        for (int i = tid; i < 2048; i += 256) {
            int frag = i >> 6, li = i & 63;
            int nt = frag >> 2, ksp = frag & 3;
            int gg = li >> 2, tt = li & 3;
            int n  = nt * 8 + gg;
            int K0 = ksp * 16;
            uint32_t b0 = packh2(m2w[(K0 + 2 * tt) * 64 + n],
                                 m2w[(K0 + 2 * tt + 1) * 64 + n]);
            uint32_t b1 = packh2(m2w[(K0 + 2 * tt + 8) * 64 + n],
                                 m2w[(K0 + 2 * tt + 9) * 64 + n]);
            sfu[frag * 64 + li] = (ull)b0 | ((ull)b1 << 32);
        }
        // edge weights: linear over E, scatter to [recv][j]
        for (int i = tid; i < Ee; i += 256) {
            int s = i / 63, t = i % 63;
            int r = t + (t >= s ? 1 : 0);
            int j = s - (s > r ? 1 : 0);
            sf[SEW + r * 64 + j] = edges[((size_t)b * Ee + i) * 2 + 1];
        }
        // node head constants
        for (int i = tid; i < 512; i += 256) {
            int k = i >> 3, a = i & 7;   // muw/lsw row-major [64][8]
            sf[SMU + a * 64 + k] = muw[i];
            sf[SLS + a * 64 + k] = lsw[i];
        }
        if (tid < 64) {
            sf[SEW + tid * 64 + 63] = 0.0f;   // pad row weight
            sf[SBIAS + tid] = m2b[tid];
            sf[SB1 + tid] = fc1b[tid];
            sf[SB2 + tid] = fc2b[tid];
        }
        if (tid < 8) {
            sf[SBM + tid] = mub[tid];
            sf[SBL + tid] = lsb[tid];
        }
        // stage x into node buf cols 0..31 (warp-private rows)
        #pragma unroll
        for (int rr = 0; rr < 8; rr++)
            sf[SBUF + (w * 8 + rr) * 104 + lane] =
                inputs[((size_t)b * 64 + w * 8 + rr) * 32 + lane];
    }
    __syncthreads();

    // ---- edge main loop ----
    #pragma unroll 1
    for (int ri = 0; ri < 8; ri++) {
        const int r = w * 8 + ri;
        const int hbbase = SHB + r * 64;

        float colacc[16];
        #pragma unroll
        for (int c = 0; c < 16; c++) colacc[c] = 0.0f;

        #pragma unroll 1
        for (int mhalf = 0; mhalf < 2; mhalf++) {
            int srow[4];
            float ewm[4];
            #pragma unroll
            for (int mi = 0; mi < 4; mi++) {
                int m = mhalf * 32 + g + mi * 8;
                int s = m + (m >= r ? 1 : 0);
                if (s > 63) s = 63;            // pad row (ew=0 kills it)
                srow[mi] = s * 68;
                ewm[mi]  = sf[SEW + r * 64 + m];
            }

            float acc[2][8][4];
            #pragma unroll
            for (int mt = 0; mt < 2; mt++)
                #pragma unroll
                for (int nt = 0; nt < 8; nt++)
                    #pragma unroll
                    for (int q = 0; q < 4; q++) acc[mt][nt][q] = 0.0f;

            #pragma unroll
            for (int ksp = 0; ksp < 4; ksp++) {
                const int kL = ksp * 16 + 2 * tig;
                const int kH = kL + 8;
                const float2 hbL = *reinterpret_cast<const float2*>(&sf[hbbase + kL]);
                const float2 hbH = *reinterpret_cast<const float2*>(&sf[hbbase + kH]);
                uint32_t a[2][4];
                #pragma unroll
                for (int mt = 0; mt < 2; mt++) {
                    const int r0 = srow[mt * 2], r1 = srow[mt * 2 + 1];
                    float2 hL0 = *reinterpret_cast<const float2*>(&sf[SHS + r0 + kL]);
                    float2 hL1 = *reinterpret_cast<const float2*>(&sf[SHS + r1 + kL]);
                    float2 hH0 = *reinterpret_cast<const float2*>(&sf[SHS + r0 + kH]);
                    float2 hH1 = *reinterpret_cast<const float2*>(&sf[SHS + r1 + kH]);
                    a[mt][0] = packh2(relu(hL0.x + hbL.x), relu(hL0.y + hbL.y));
                    a[mt][1] = packh2(relu(hL1.x + hbL.x), relu(hL1.y + hbL.y));
                    a[mt][2] = packh2(relu(hH0.x + hbH.x), relu(hH0.y + hbH.y));
                    a[mt][3] = packh2(relu(hH1.x + hbH.x), relu(hH1.y + hbH.y));
                }
                #pragma unroll
                for (int nt = 0; nt < 8; nt++) {
                    ull bv = sfu[(nt * 4 + ksp) * 64 + lane];
                    uint32_t b0 = (uint32_t)bv;
                    uint32_t b1 = (uint32_t)(bv >> 32);
                    mma_f16(acc[0][nt], a[0], b0, b1);
                    mma_f16(acc[1][nt], a[1], b0, b1);
                }
            }

            #pragma unroll
            for (int nt = 0; nt < 8; nt++) {
                float bs0 = sf[SBIAS + nt * 8 + 2 * tig];
                float bs1 = sf[SBIAS + nt * 8 + 2 * tig + 1];
                #pragma unroll
                for (int mt = 0; mt < 2; mt++) {
                    float ew0 = ewm[mt * 2];
                    float ew1 = ewm[mt * 2 + 1];
                    float* c4 = acc[mt][nt];
                    colacc[nt * 2]     += relu(c4[0] + bs0) * ew0
                                        + relu(c4[2] + bs0) * ew1;
                    colacc[nt * 2 + 1] += relu(c4[1] + bs1) * ew0
                                        + relu(c4[3] + bs1) * ew1;
                }
            }
        }

        #pragma unroll
        for (int c = 0; c < 16; c++) {
            colacc[c] += __shfl_xor_sync(FULL, colacc[c], 4);
            colacc[c] += __shfl_xor_sync(FULL, colacc[c], 8);
            colacc[c] += __shfl_xor_sync(FULL, colacc[c], 16);
        }
        float v0 = 0.0f, v1 = 0.0f;
        #pragma unroll
        for (int nt = 0; nt < 8; nt++)
            if (g == nt) { v0 = colacc[nt * 2]; v1 = colacc[nt * 2 + 1]; }
        // gmem output + node buf (warp-private)
        *reinterpret_cast<float2*>(
            &out[OUT_AUG + ((size_t)b * 64 + r) * 96 + 32 + g * 8 + 2 * tig]) =
            make_float2(v0, v1);
        *reinterpret_cast<float2*>(
            &sf[SBUF + r * 104 + 32 + g * 8 + 2 * tig]) = make_float2(v0, v1);
    }
    __syncwarp();

    // ---- node head tail (rows b*64 + w*8 .. +7) ----
    {
        const int rowbase = b * 64 + w * 8;
        const int bufbase = SBUF + w * 8 * 104;

        ull alo[8], ahi[8];
        #pragma unroll
        for (int rr = 0; rr < 8; rr++) { alo[rr] = 0ull; ahi[rr] = 0ull; }
        #pragma unroll 1
        for (int kp4 = 0; kp4 < 12; kp4++) {
            ull wl[4], wh[4];
            #pragma unroll
            for (int j = 0; j < 4; j++) {
                wl[j] = __ldg(&g_w1I[(kp4 * 4 + j) * 64 + lane]);
                wh[j] = __ldg(&g_w1I[(kp4 * 4 + j) * 64 + lane + 32]);
            }
            #pragma unroll
            for (int rr = 0; rr < 8; rr++) {
                const ull2* hp = reinterpret_cast<const ull2*>(
                    &sf[bufbase + rr * 104 + kp4 * 8]);
                ull2 ha = hp[0];
                ull2 hb2 = hp[1];
                alo[rr] = fma2(ha.x,  wl[0], alo[rr]);  ahi[rr] = fma2(ha.x,  wh[0], ahi[rr]);
                alo[rr] = fma2(ha.y,  wl[1], alo[rr]);  ahi[rr] = fma2(ha.y,  wh[1], ahi[rr]);
                alo[rr] = fma2(hb2.x, wl[2], alo[rr]);  ahi[rr] = fma2(hb2.x, wh[2], ahi[rr]);
                alo[rr] = fma2(hb2.y, wl[3], alo[rr]);  ahi[rr] = fma2(hb2.y, wh[3], ahi[rr]);
            }
        }
        __syncwarp();
        {
            const float b0 = sf[SB1 + lane], b1 = sf[SB1 + lane + 32];
            #pragma unroll
            for (int rr = 0; rr < 8; rr++) {
                float2 pl = *reinterpret_cast<float2*>(&alo[rr]);
                float2 ph = *reinterpret_cast<float2*>(&ahi[rr]);
                sf[bufbase + rr * 104 + lane]      = relu(pl.x + pl.y + b0);
                sf[bufbase + rr * 104 + lane + 32] = relu(ph.x + ph.y + b1);
            }
        }
        __syncwarp();

        #pragma unroll
        for (int rr = 0; rr < 8; rr++) { alo[rr] = 0ull; ahi[rr] = 0ull; }
        #pragma unroll 1
        for (int kp4 = 0; kp4 < 8; kp4++) {
            ull wl[4], wh[4];
            #pragma unroll
            for (int j = 0; j < 4; j++) {
                wl[j] = __ldg(&g_w2I[(kp4 * 4 + j) * 64 + lane]);
                wh[j] = __ldg(&g_w2I[(kp4 * 4 + j) * 64 + lane + 32]);
            }
            #pragma unroll
            for (int rr = 0; rr < 8; rr++) {
                const ull2* hp = reinterpret_cast<const ull2*>(
                    &sf[bufbase + rr * 104 + kp4 * 8]);
                ull2 ha = hp[0];
                ull2 hb2 = hp[1];
                alo[rr] = fma2(ha.x,  wl[0], alo[rr]);  ahi[rr] = fma2(ha.x,  wh[0], ahi[rr]);
                alo[rr] = fma2(ha.y,  wl[1], alo[rr]);  ahi[rr] = fma2(ha.y,  wh[1], ahi[rr]);
                alo[rr] = fma2(hb2.x, wl[2], alo[rr]);  ahi[rr] = fma2(hb2.x, wh[2], ahi[rr]);
                alo[rr] = fma2(hb2.y, wl[3], alo[rr]);  ahi[rr] = fma2(hb2.y, wh[3], ahi[rr]);
            }
        }
        __syncwarp();
        {
            const float b0 = sf[SB2 + lane], b1 = sf[SB2 + lane + 32];
            #pragma unroll
            for (int rr = 0; rr < 8; rr++) {
                float2 pl = *reinterpret_cast<float2*>(&alo[rr]);
                float2 ph = *reinterpret_cast<float2*>(&ahi[rr]);
                sf[bufbase + rr * 104 + lane]      = relu(pl.x + pl.y + b0);
                sf[bufbase + rr * 104 + lane + 32] = relu(ph.x + ph.y + b1);
            }
        }
        __syncwarp();

        const int a   = lane >> 2;
        const int seg = lane & 3;
        #pragma unroll 1
        for (int rr = 0; rr < 8; rr++) {
            const int row = rowbase + rr;
            const float* trow = &sf[bufbase + rr * 104];
            float pm = 0.f, pl = 0.f;
            #pragma unroll
            for (int j4 = 0; j4 < 4; j4++) {
                int k = seg * 16 + j4 * 4;
                float4 tv = *reinterpret_cast<const float4*>(trow + k);
                float4 mv = *reinterpret_cast<const float4*>(&sf[SMU + a * 64 + k]);
                float4 lv = *reinterpret_cast<const float4*>(&sf[SLS + a * 64 + k]);
                pm = fmaf(tv.x, mv.x, pm); pm = fmaf(tv.y, mv.y, pm);
                pm = fmaf(tv.z, mv.z, pm); pm = fmaf(tv.w, mv.w, pm);
                pl = fmaf(tv.x, lv.x, pl); pl = fmaf(tv.y, lv.y, pl);
                pl = fmaf(tv.z, lv.z, pl); pl = fmaf(tv.w, lv.w, pl);
            }
            pm += __shfl_xor_sync(FULL, pm, 1); pm += __shfl_xor_sync(FULL, pm, 2);
            pl += __shfl_xor_sync(FULL, pl, 1); pl += __shfl_xor_sync(FULL, pl, 2);

            float mu = pm + sf[SBM + a];
            float ls = fminf(fmaxf(pl + sf[SBL + a], -3.0f), 1.0f);
            float x  = -2.0f * mu;
            float sp = fmaxf(x, 0.0f) + log1pf(expf(-fabsf(x)));
            float c  = -ls - HALF_LOG_2PI_F - 2.0f * (LOG2_F - mu - sp);

            if (seg == 0) out[OUT_TANH + (size_t)row * Aa + a] = tanhf(mu);

            float val = (seg == 0) ? c : 0.f;
            val += __shfl_xor_sync(FULL, val, 4);
            val += __shfl_xor_sync(FULL, val, 8);
            val += __shfl_xor_sync(FULL, val, 16);
            if (lane == 0) out[OUT_LOGP + row] = val;
        }
    }
}

extern "C" void kernel_launch(void* const* d_in, const int* in_sizes, int n_in,
                              void* d_out, int out_size) {
    (void)in_sizes; (void)n_in; (void)out_size;
    const float* inputs = (const float*)d_in[0];
    const float* edges  = (const float*)d_in[1];
    const float* m1w    = (const float*)d_in[2];
    const float* m1b    = (const float*)d_in[3];
    const float* m2w    = (const float*)d_in[4];
    const float* m2b    = (const float*)d_in[5];
    const float* fc1w   = (const float*)d_in[6];
    const float* fc1b   = (const float*)d_in[7];
    const float* fc2w   = (const float*)d_in[8];
    const float* fc2b   = (const float*)d_in[9];
    const float* muw    = (const float*)d_in[10];
    const float* mub    = (const float*)d_in[11];
    const float* lsw    = (const float*)d_in[12];
    const float* lsb    = (const float*)d_in[13];
    float* out = (float*)d_out;

    cudaFuncSetAttribute(edge_kernel,
                         cudaFuncAttributeMaxDynamicSharedMemorySize, EDGE_SMEM_B);

    mlp1_kernel<<<1024, 256>>>(inputs, m1w, m1b, fc1w, fc2w, out);
    edge_kernel<<<512, 256, EDGE_SMEM_B>>>(
        inputs, edges, m2w, m2b, fc1b, fc2b, muw, mub, lsw, lsb, out);
}

// round 14
// speedup vs baseline: 1.2874x; 1.1180x over previous
#include <cuda_runtime.h>
#include <cstdint>

#define FULL 0xffffffffu
typedef unsigned long long ull;
typedef ulonglong2 ull2;

// Problem dims
constexpr int Bb = 512;
constexpr int Vv = 64;
constexpr int Aa = 8;
constexpr int Ee = Vv * (Vv - 1);   // 4032

// Output layout: [tanh_mu B*V*A][logp B*V][aug B*V*96]
constexpr size_t OUT_TANH = 0;
constexpr size_t OUT_LOGP = (size_t)Bb * Vv * Aa;          // 262144
constexpr size_t OUT_AUG  = OUT_LOGP + (size_t)Bb * Vv;    // 294912

__device__ __forceinline__ float relu(float x) { return fmaxf(x, 0.0f); }

constexpr float HALF_LOG_2PI_F = 0.91893853320467274f;
constexpr float LOG2_F         = 0.69314718055994531f;

// ---- packed fp32x2 helpers ----
__device__ __forceinline__ ull fma2(ull a, ull b, ull c) {
    ull d;
    asm("fma.rn.f32x2 %0, %1, %2, %3;" : "=l"(d) : "l"(a), "l"(b), "l"(c));
    return d;
}
__device__ __forceinline__ ull packdup(float x) {
    ull d;
    asm("mov.b64 %0, {%1, %1};" : "=l"(d) : "f"(x));
    return d;
}
__device__ __forceinline__ ull pack2(float lo, float hi) {
    ull d;
    asm("mov.b64 %0, {%1, %2};" : "=l"(d) : "f"(lo), "f"(hi));
    return d;
}
// pack two fp32 into half2: lo -> bits[15:0], hi -> bits[31:16]
__device__ __forceinline__ uint32_t packh2(float lo, float hi) {
    uint32_t d;
    asm("cvt.rn.f16x2.f32 %0, %1, %2;" : "=r"(d) : "f"(hi), "f"(lo));
    return d;
}
// half2 add / relu
__device__ __forceinline__ uint32_t hadd2(uint32_t a, uint32_t b) {
    uint32_t d;
    asm("add.f16x2 %0, %1, %2;" : "=r"(d) : "r"(a), "r"(b));
    return d;
}
__device__ __forceinline__ uint32_t hrelu2(uint32_t a) {
    uint32_t d;
    asm("max.f16x2 %0, %1, %2;" : "=r"(d) : "r"(a), "r"(0u));
    return d;
}

// m16n8k16 f16 mma, f32 accumulate (sm_80+ path, legal on plain sm_103)
__device__ __forceinline__ void mma_f16(float c[4], const uint32_t a[4],
                                        uint32_t b0, uint32_t b1) {
    asm volatile(
        "mma.sync.aligned.m16n8k16.row.col.f32.f16.f16.f32 "
        "{%0,%1,%2,%3}, {%4,%5,%6,%7}, {%8,%9}, {%0,%1,%2,%3};"
        : "+f"(c[0]), "+f"(c[1]), "+f"(c[2]), "+f"(c[3])
        : "r"(a[0]), "r"(a[1]), "r"(a[2]), "r"(a[3]), "r"(b0), "r"(b1));
}

// Scratch for MLP1 halves + prepacked node weights
__device__ float g_hb[(size_t)Bb * Vv * 64];
__device__ float g_hs[(size_t)Bb * Vv * 64];
__device__ ull   g_w1I[48 * 64];   // fc1w interleaved [kpair][c]
__device__ ull   g_w2I[32 * 64];   // fc2w interleaved

// ============================================================================
// Kernel 0: MLP1 halves per (b,v); copies inputs into aug[:,0:32].
// Block 0 additionally prepacks the node weights into g_w1I/g_w2I.
// ============================================================================
__global__ __launch_bounds__(256) void mlp1_kernel(
    const float* __restrict__ inputs,   // [B*V, 32]
    const float* __restrict__ m1w,      // [64,64]
    const float* __restrict__ m1b,      // [64]
    const float* __restrict__ fc1w,     // [96,64]
    const float* __restrict__ fc2w,     // [64,64]
    float* __restrict__ out)
{
    __shared__ ull wr[32][32];
    __shared__ ull ws[32][32];
    __shared__ ull sbb[32];

    const int tid = threadIdx.x;
    if (blockIdx.x == 0) {
        for (int i = tid; i < 48 * 64; i += 256) {
            int kp = i >> 6, c = i & 63;
            g_w1I[i] = pack2(fc1w[(2 * kp) * 64 + c], fc1w[(2 * kp + 1) * 64 + c]);
        }
        for (int i = tid; i < 32 * 64; i += 256) {
            int kp = i >> 6, c = i & 63;
            g_w2I[i] = pack2(fc2w[(2 * kp) * 64 + c], fc2w[(2 * kp + 1) * 64 + c]);
        }
    }
    for (int i = tid; i < 32 * 32; i += 256) {
        int k = i >> 5, c = i & 31;
        wr[k][c] = pack2(m1w[k * 64 + c],        m1w[k * 64 + c + 32]);
        ws[k][c] = pack2(m1w[(32 + k) * 64 + c], m1w[(32 + k) * 64 + c + 32]);
    }
    if (tid < 32) sbb[tid] = pack2(m1b[tid], m1b[tid + 32]);
    __syncthreads();

    const int lane = tid & 31;
    const int w    = tid >> 5;
    const size_t baserow = (size_t)blockIdx.x * 32 + w * 4;

    float xv[4];
    ull ab[4], as2[4];
    #pragma unroll
    for (int q = 0; q < 4; q++) {
        xv[q]  = inputs[(baserow + q) * 32 + lane];
        ab[q]  = sbb[lane];
        as2[q] = 0ull;
    }
    #pragma unroll
    for (int k = 0; k < 32; k++) {
        ull wrk = wr[k][lane];
        ull wsk = ws[k][lane];
        #pragma unroll
        for (int q = 0; q < 4; q++) {
            ull p = packdup(__shfl_sync(FULL, xv[q], k));
            ab[q]  = fma2(p, wrk, ab[q]);
            as2[q] = fma2(p, wsk, as2[q]);
        }
    }
    #pragma unroll
    for (int q = 0; q < 4; q++) {
        size_t row = baserow + q;
        float2 fb = *reinterpret_cast<float2*>(&ab[q]);
        float2 fs = *reinterpret_cast<float2*>(&as2[q]);
        g_hb[row * 64 + lane]      = fb.x;
        g_hb[row * 64 + lane + 32] = fb.y;
        g_hs[row * 64 + lane]      = fs.x;
        g_hs[row * 64 + lane + 32] = fs.y;
        out[OUT_AUG + row * 96 + lane] = xv[q];   // aug[:, 0:32]
    }
}

// ============================================================================
// Kernel 1: FUSED edge MLP2 (fp16 mma, half2 h-build) + agg + node MLP head.
// hs/hb stored in smem as packed half2 -> a-fragments via add.f16x2/max.f16x2,
// no per-element cvt, half the LDS bytes, conflict-free stride-36 layout.
// ============================================================================
constexpr int SHSH  = 0;                   // hs half2 [64][36] uints
constexpr int SHBH  = 64 * 36;             // hb half2 [64][32] uints
constexpr int SBF   = SHBH + 64 * 32;      // B frags: 32x64 ull (4096 floats)
constexpr int SEW   = SBF + 4096;          // ew [64][64]
constexpr int SBIAS = SEW + 4096;          // m2b [64]
constexpr int SBUF  = SBIAS + 64;          // node buf [8][8][104]
constexpr int SMU   = SBUF + 8 * 8 * 104;  // muw^T [8][64]
constexpr int SLS   = SMU + 512;           // lsw^T [8][64]
constexpr int SB1   = SLS + 512;           // fc1b [64]
constexpr int SB2   = SB1 + 64;            // fc2b [64]
constexpr int SBM   = SB2 + 64;            // mub [8]
constexpr int SBL   = SBM + 8;             // lsb [8]
constexpr int EDGE_SMEM_F = SBL + 8;
constexpr int EDGE_SMEM_B = EDGE_SMEM_F * 4;   // ~82 KB

__global__ __launch_bounds__(256, 2) void edge_kernel(
    const float* __restrict__ inputs,   // [B,V,32]
    const float* __restrict__ edges,    // [B,E,2]
    const float* __restrict__ m2w,      // [64,64]
    const float* __restrict__ m2b,      // [64]
    const float* __restrict__ fc1b,
    const float* __restrict__ fc2b,
    const float* __restrict__ muw,      // [64,8]
    const float* __restrict__ mub,
    const float* __restrict__ lsw,      // [64,8]
    const float* __restrict__ lsb,
    float* __restrict__ out)
{
    extern __shared__ float sf[];
    uint32_t* sfui = reinterpret_cast<uint32_t*>(sf);
    ull* sfu = reinterpret_cast<ull*>(&sf[SBF]);

    const int b    = blockIdx.x;
    const int tid  = threadIdx.x;
    const int lane = tid & 31;
    const int w    = tid >> 5;
    const int g    = lane >> 2;   // group id (rows / n-cols)
    const int tig  = lane & 3;    // thread in group

    // ---- prologue ----
    {
        const float* hs_g = g_hs + (size_t)b * 4096;
        const float* hb_g = g_hb + (size_t)b * 4096;
        // pack hs/hb fp32 pairs -> half2 smem
        for (int i = tid; i < 2048; i += 256) {
            int row = i >> 5, j = i & 31;
            float2 vs = *reinterpret_cast<const float2*>(&hs_g[row * 64 + 2 * j]);
            float2 vb = *reinterpret_cast<const float2*>(&hb_g[row * 64 + 2 * j]);
            sfui[SHSH + row * 36 + j] = packh2(vs.x, vs.y);
            sfui[SHBH + row * 32 + j] = packh2(vb.x, vb.y);
        }
        // B fragments (fragment-major, fp16)
        for (int i = tid; i < 2048; i += 256) {
            int frag = i >> 6, li = i & 63;
            int nt = frag >> 2, ksp = frag & 3;
            int gg = li >> 2, tt = li & 3;
            int n  = nt * 8 + gg;
            int K0 = ksp * 16;
            uint32_t b0 = packh2(m2w[(K0 + 2 * tt) * 64 + n],
                                 m2w[(K0 + 2 * tt + 1) * 64 + n]);
            uint32_t b1 = packh2(m2w[(K0 + 2 * tt + 8) * 64 + n],
                                 m2w[(K0 + 2 * tt + 9) * 64 + n]);
            sfu[frag * 64 + li] = (ull)b0 | ((ull)b1 << 32);
        }
        // edge weights: linear over E, scatter to [recv][j]
        for (int i = tid; i < Ee; i += 256) {
            int s = i / 63, t = i % 63;
            int r = t + (t >= s ? 1 : 0);
            int j = s - (s > r ? 1 : 0);
            sf[SEW + r * 64 + j] = edges[((size_t)b * Ee + i) * 2 + 1];
        }
        // node head constants
        for (int i = tid; i < 512; i += 256) {
            int k = i >> 3, a = i & 7;   // muw/lsw row-major [64][8]
            sf[SMU + a * 64 + k] = muw[i];
            sf[SLS + a * 64 + k] = lsw[i];
        }
        if (tid < 64) {
            sf[SEW + tid * 64 + 63] = 0.0f;   // pad row weight
            sf[SBIAS + tid] = m2b[tid];
            sf[SB1 + tid] = fc1b[tid];
            sf[SB2 + tid] = fc2b[tid];
        }
        if (tid < 8) {
            sf[SBM + tid] = mub[tid];
            sf[SBL + tid] = lsb[tid];
        }
        // stage x into node buf cols 0..31 (warp-private rows)
        #pragma unroll
        for (int rr = 0; rr < 8; rr++)
            sf[SBUF + (w * 8 + rr) * 104 + lane] =
                inputs[((size_t)b * 64 + w * 8 + rr) * 32 + lane];
    }
    __syncthreads();

    // ---- edge main loop ----
    #pragma unroll 1
    for (int ri = 0; ri < 8; ri++) {
        const int r = w * 8 + ri;
        const int hbbase = SHBH + r * 32;

        float colacc[16];
        #pragma unroll
        for (int c = 0; c < 16; c++) colacc[c] = 0.0f;

        #pragma unroll 1
        for (int mhalf = 0; mhalf < 2; mhalf++) {
            int srow[4];
            float ewm[4];
            #pragma unroll
            for (int mi = 0; mi < 4; mi++) {
                int m = mhalf * 32 + g + mi * 8;
                int s = m + (m >= r ? 1 : 0);
                if (s > 63) s = 63;            // pad row (ew=0 kills it)
                srow[mi] = SHSH + s * 36;
                ewm[mi]  = sf[SEW + r * 64 + m];
            }

            float acc[2][8][4];
            #pragma unroll
            for (int mt = 0; mt < 2; mt++)
                #pragma unroll
                for (int nt = 0; nt < 8; nt++)
                    #pragma unroll
                    for (int q = 0; q < 4; q++) acc[mt][nt][q] = 0.0f;

            #pragma unroll
            for (int ksp = 0; ksp < 4; ksp++) {
                const int jL = ksp * 8 + tig;     // half2 index (k=2jL, 2jL+1)
                const uint32_t hbL = sfui[hbbase + jL];
                const uint32_t hbH = sfui[hbbase + jL + 4];
                uint32_t a[2][4];
                #pragma unroll
                for (int mt = 0; mt < 2; mt++) {
                    const int r0 = srow[mt * 2], r1 = srow[mt * 2 + 1];
                    a[mt][0] = hrelu2(hadd2(sfui[r0 + jL],     hbL));
                    a[mt][1] = hrelu2(hadd2(sfui[r1 + jL],     hbL));
                    a[mt][2] = hrelu2(hadd2(sfui[r0 + jL + 4], hbH));
                    a[mt][3] = hrelu2(hadd2(sfui[r1 + jL + 4], hbH));
                }
                #pragma unroll
                for (int nt = 0; nt < 8; nt++) {
                    ull bv = sfu[(nt * 4 + ksp) * 64 + lane];
                    uint32_t b0 = (uint32_t)bv;
                    uint32_t b1 = (uint32_t)(bv >> 32);
                    mma_f16(acc[0][nt], a[0], b0, b1);
                    mma_f16(acc[1][nt], a[1], b0, b1);
                }
            }

            #pragma unroll
            for (int nt = 0; nt < 8; nt++) {
                float bs0 = sf[SBIAS + nt * 8 + 2 * tig];
                float bs1 = sf[SBIAS + nt * 8 + 2 * tig + 1];
                #pragma unroll
                for (int mt = 0; mt < 2; mt++) {
                    float ew0 = ewm[mt * 2];
                    float ew1 = ewm[mt * 2 + 1];
                    float* c4 = acc[mt][nt];
                    colacc[nt * 2]     += relu(c4[0] + bs0) * ew0
                                        + relu(c4[2] + bs0) * ew1;
                    colacc[nt * 2 + 1] += relu(c4[1] + bs1) * ew0
                                        + relu(c4[3] + bs1) * ew1;
                }
            }
        }

        #pragma unroll
        for (int c = 0; c < 16; c++) {
            colacc[c] += __shfl_xor_sync(FULL, colacc[c], 4);
            colacc[c] += __shfl_xor_sync(FULL, colacc[c], 8);
            colacc[c] += __shfl_xor_sync(FULL, colacc[c], 16);
        }
        float v0 = 0.0f, v1 = 0.0f;
        #pragma unroll
        for (int nt = 0; nt < 8; nt++)
            if (g == nt) { v0 = colacc[nt * 2]; v1 = colacc[nt * 2 + 1]; }
        *reinterpret_cast<float2*>(
            &out[OUT_AUG + ((size_t)b * 64 + r) * 96 + 32 + g * 8 + 2 * tig]) =
            make_float2(v0, v1);
        *reinterpret_cast<float2*>(
            &sf[SBUF + r * 104 + 32 + g * 8 + 2 * tig]) = make_float2(v0, v1);
    }
    __syncwarp();

    // ---- node head tail (rows b*64 + w*8 .. +7) ----
    {
        const int rowbase = b * 64 + w * 8;
        const int bufbase = SBUF + w * 8 * 104;

        ull alo[8], ahi[8];
        #pragma unroll
        for (int rr = 0; rr < 8; rr++) { alo[rr] = 0ull; ahi[rr] = 0ull; }
        #pragma unroll 1
        for (int kp4 = 0; kp4 < 12; kp4++) {
            ull wl[4], wh[4];
            #pragma unroll
            for (int j = 0; j < 4; j++) {
                wl[j] = __ldg(&g_w1I[(kp4 * 4 + j) * 64 + lane]);
                wh[j] = __ldg(&g_w1I[(kp4 * 4 + j) * 64 + lane + 32]);
            }
            #pragma unroll
            for (int rr = 0; rr < 8; rr++) {
                const ull2* hp = reinterpret_cast<const ull2*>(
                    &sf[bufbase + rr * 104 + kp4 * 8]);
                ull2 ha = hp[0];
                ull2 hb2 = hp[1];
                alo[rr] = fma2(ha.x,  wl[0], alo[rr]);  ahi[rr] = fma2(ha.x,  wh[0], ahi[rr]);
                alo[rr] = fma2(ha.y,  wl[1], alo[rr]);  ahi[rr] = fma2(ha.y,  wh[1], ahi[rr]);
                alo[rr] = fma2(hb2.x, wl[2], alo[rr]);  ahi[rr] = fma2(hb2.x, wh[2], ahi[rr]);
                alo[rr] = fma2(hb2.y, wl[3], alo[rr]);  ahi[rr] = fma2(hb2.y, wh[3], ahi[rr]);
            }
        }
        __syncwarp();
        {
            const float b0 = sf[SB1 + lane], b1 = sf[SB1 + lane + 32];
            #pragma unroll
            for (int rr = 0; rr < 8; rr++) {
                float2 pl = *reinterpret_cast<float2*>(&alo[rr]);
                float2 ph = *reinterpret_cast<float2*>(&ahi[rr]);
                sf[bufbase + rr * 104 + lane]      = relu(pl.x + pl.y + b0);
                sf[bufbase + rr * 104 + lane + 32] = relu(ph.x + ph.y + b1);
            }
        }
        __syncwarp();

        #pragma unroll
        for (int rr = 0; rr < 8; rr++) { alo[rr] = 0ull; ahi[rr] = 0ull; }
        #pragma unroll 1
        for (int kp4 = 0; kp4 < 8; kp4++) {
            ull wl[4], wh[4];
            #pragma unroll
            for (int j = 0; j < 4; j++) {
                wl[j] = __ldg(&g_w2I[(kp4 * 4 + j) * 64 + lane]);
                wh[j] = __ldg(&g_w2I[(kp4 * 4 + j) * 64 + lane + 32]);
            }
            #pragma unroll
            for (int rr = 0; rr < 8; rr++) {
                const ull2* hp = reinterpret_cast<const ull2*>(
                    &sf[bufbase + rr * 104 + kp4 * 8]);
                ull2 ha = hp[0];
                ull2 hb2 = hp[1];
                alo[rr] = fma2(ha.x,  wl[0], alo[rr]);  ahi[rr] = fma2(ha.x,  wh[0], ahi[rr]);
                alo[rr] = fma2(ha.y,  wl[1], alo[rr]);  ahi[rr] = fma2(ha.y,  wh[1], ahi[rr]);
                alo[rr] = fma2(hb2.x, wl[2], alo[rr]);  ahi[rr] = fma2(hb2.x, wh[2], ahi[rr]);
                alo[rr] = fma2(hb2.y, wl[3], alo[rr]);  ahi[rr] = fma2(hb2.y, wh[3], ahi[rr]);
            }
        }
        __syncwarp();
        {
            const float b0 = sf[SB2 + lane], b1 = sf[SB2 + lane + 32];
            #pragma unroll
            for (int rr = 0; rr < 8; rr++) {
                float2 pl = *reinterpret_cast<float2*>(&alo[rr]);
                float2 ph = *reinterpret_cast<float2*>(&ahi[rr]);
                sf[bufbase + rr * 104 + lane]      = relu(pl.x + pl.y + b0);
                sf[bufbase + rr * 104 + lane + 32] = relu(ph.x + ph.y + b1);
            }
        }
        __syncwarp();

        const int a   = lane >> 2;
        const int seg = lane & 3;
        #pragma unroll 1
        for (int rr = 0; rr < 8; rr++) {
            const int row = rowbase + rr;
            const float* trow = &sf[bufbase + rr * 104];
            float pm = 0.f, pl = 0.f;
            #pragma unroll
            for (int j4 = 0; j4 < 4; j4++) {
                int k = seg * 16 + j4 * 4;
                float4 tv = *reinterpret_cast<const float4*>(trow + k);
                float4 mv = *reinterpret_cast<const float4*>(&sf[SMU + a * 64 + k]);
                float4 lv = *reinterpret_cast<const float4*>(&sf[SLS + a * 64 + k]);
                pm = fmaf(tv.x, mv.x, pm); pm = fmaf(tv.y, mv.y, pm);
                pm = fmaf(tv.z, mv.z, pm); pm = fmaf(tv.w, mv.w, pm);
                pl = fmaf(tv.x, lv.x, pl); pl = fmaf(tv.y, lv.y, pl);
                pl = fmaf(tv.z, lv.z, pl); pl = fmaf(tv.w, lv.w, pl);
            }
            pm += __shfl_xor_sync(FULL, pm, 1); pm += __shfl_xor_sync(FULL, pm, 2);
            pl += __shfl_xor_sync(FULL, pl, 1); pl += __shfl_xor_sync(FULL, pl, 2);

            float mu = pm + sf[SBM + a];
            float ls = fminf(fmaxf(pl + sf[SBL + a], -3.0f), 1.0f);
            float x  = -2.0f * mu;
            float sp = fmaxf(x, 0.0f) + log1pf(expf(-fabsf(x)));
            float c  = -ls - HALF_LOG_2PI_F - 2.0f * (LOG2_F - mu - sp);

            if (seg == 0) out[OUT_TANH + (size_t)row * Aa + a] = tanhf(mu);

            float val = (seg == 0) ? c : 0.f;
            val += __shfl_xor_sync(FULL, val, 4);
            val += __shfl_xor_sync(FULL, val, 8);
            val += __shfl_xor_sync(FULL, val, 16);
            if (lane == 0) out[OUT_LOGP + row] = val;
        }
    }
}

extern "C" void kernel_launch(void* const* d_in, const int* in_sizes, int n_in,
                              void* d_out, int out_size) {
    (void)in_sizes; (void)n_in; (void)out_size;
    const float* inputs = (const float*)d_in[0];
    const float* edges  = (const float*)d_in[1];
    const float* m1w    = (const float*)d_in[2];
    const float* m1b    = (const float*)d_in[3];
    const float* m2w    = (const float*)d_in[4];
    const float* m2b    = (const float*)d_in[5];
    const float* fc1w   = (const float*)d_in[6];
    const float* fc1b   = (const float*)d_in[7];
    const float* fc2w   = (const float*)d_in[8];
    const float* fc2b   = (const float*)d_in[9];
    const float* muw    = (const float*)d_in[10];
    const float* mub    = (const float*)d_in[11];
    const float* lsw    = (const float*)d_in[12];
    const float* lsb    = (const float*)d_in[13];
    float* out = (float*)d_out;

    cudaFuncSetAttribute(edge_kernel,
                         cudaFuncAttributeMaxDynamicSharedMemorySize, EDGE_SMEM_B);

    mlp1_kernel<<<1024, 256>>>(inputs, m1w, m1b, fc1w, fc2w, out);
    edge_kernel<<<512, 256, EDGE_SMEM_B>>>(
        inputs, edges, m2w, m2b, fc1b, fc2b, muw, mub, lsw, lsb, out);
}